// round 1
// baseline (speedup 1.0000x reference)
#include <cuda_runtime.h>
#include <cstdint>

// DepenL: out1[b,c,m] = Uk[b,c,m] * Uq[b,c,(m/9)*9+4]
//         out2[b,c,m] = Uk[b,c,(m/9)*9+4] * Uq[b,c,m]
// where U is the raw-reinterpreted unfold: for flat m in [0, 9L),
//   p = m / L, l = m % L, (i,j) = (p/3-1, p%3-1), (h,w) = (l/128, l%128),
//   U[m] = x[b,c,h+i,w+j]  (0 if outside, i.e. zero pad).
//
// B=4, C=64, H=W=128, L=16384, M=9L=147456. Output: out1 then out2, each B*C*M.

#define DL_L      16384
#define DL_M      147456      // 9*L
#define DL_BC     256         // B*C
#define DL_THREADS 256

__global__ __launch_bounds__(DL_THREADS)
void depenl_kernel(const float* __restrict__ key,
                   const float* __restrict__ query,
                   float* __restrict__ out1,
                   float* __restrict__ out2) {
    const int bc = blockIdx.y;
    const int m0 = (blockIdx.x * DL_THREADS + threadIdx.x) * 4;
    // grid sized exactly: 147456 / (4*256) = 144 blocks in x, no bounds check needed

    const float* __restrict__ kb = key   + (size_t)bc * DL_L;
    const float* __restrict__ qb = query + (size_t)bc * DL_L;

    // p and h are constant across the 4-element group (L and W divisible by 4)
    const int p  = m0 >> 14;            // m0 / L
    const int i  = (p * 11) >> 5;       // p/3 for p in 0..8
    const int j  = p - i * 3 - 1;       // col offset -1..1
    const int l0 = m0 & 16383;
    const int h  = l0 >> 7;
    const int w0 = l0 & 127;
    const int hh = h + i - 1;           // row offset folded: i-1 in {-1,0,1}
    const bool hok = (unsigned)hh < 128u;
    const int rowbase = hh << 7;

    float r1[4], r2[4];
#pragma unroll
    for (int e = 0; e < 4; e++) {
        const int mm = m0 + e;
        // neighbor element (same for key and query)
        const int ww = w0 + e + j;
        const bool nok = hok && ((unsigned)ww < 128u);
        const int nidx = rowbase + ww;
        const float knb = nok ? __ldg(kb + nidx) : 0.0f;
        const float qnb = nok ? __ldg(qb + nidx) : 0.0f;
        // "center" slice index under the raw reinterpretation
        const int g  = mm / 9;          // compiler -> mul-hi
        const int mc = g * 9 + 4;
        const int pc = mc >> 14;
        const int lc = mc & 16383;
        const int ic = (pc * 11) >> 5;  // pc/3
        const int jc = pc - ic * 3 - 1;
        const int hc = (lc >> 7) + ic - 1;
        const int wc = (lc & 127) + jc;
        const bool cok = ((unsigned)hc < 128u) && ((unsigned)wc < 128u);
        const int cidx = (hc << 7) + wc;
        const float kc = cok ? __ldg(kb + cidx) : 0.0f;
        const float qc = cok ? __ldg(qb + cidx) : 0.0f;

        r1[e] = knb * qc;   // Uk[m]  * Uq[mc]
        r2[e] = kc  * qnb;  // Uk[mc] * Uq[m]
    }

    const size_t obase = (size_t)bc * DL_M + m0;   // multiple of 4 -> 16B aligned
    *reinterpret_cast<float4*>(out1 + obase) = make_float4(r1[0], r1[1], r1[2], r1[3]);
    *reinterpret_cast<float4*>(out2 + obase) = make_float4(r2[0], r2[1], r2[2], r2[3]);
}

extern "C" void kernel_launch(void* const* d_in, const int* in_sizes, int n_in,
                              void* d_out, int out_size) {
    const float* key   = (const float*)d_in[0];   // key_map   [4,64,128,128] f32
    const float* query = (const float*)d_in[1];   // query_map [4,64,128,128] f32
    float* out1 = (float*)d_out;
    float* out2 = out1 + (size_t)DL_BC * DL_M;    // second tensor of the tuple

    dim3 grid(DL_M / (4 * DL_THREADS), DL_BC);    // (144, 256)
    depenl_kernel<<<grid, DL_THREADS>>>(key, query, out1, out2);
}

// round 3
// speedup vs baseline: 1.2072x; 1.2072x over previous
#include <cuda_runtime.h>
#include <cstdint>

// DepenL via tiled shared-memory formulation.
//
// Within one channel (9L floats of unfold, L=16384), for m = p*L + l:
//   U[m] = x[h+i-1, w+j-1], h=l/128, w=l%128, i=p/3, j=p%3 (0 outside image).
//   out1[m] = Uk[m] * Uq[mc],  out2[m] = Uk[mc] * Uq[m],  mc = 9*(m/9)+4.
// Since L mod 9 == 4:  mc = m + d,  d = 4 - ((4p + l) mod 9) in [-4,4].
// If l+d in [0,L): center = U[p, l+d]  (same p, nearby pixel) -> shared memory.
// Else (<=8 elems per p-segment): full decode + global fallback.

#define WW   128
#define LL   16384
#define MM   147456   // 9*L
#define HC   16       // rows per block chunk
#define NR   (HC + 4) // stored rows (halo 2 each side)
#define RS   136      // smem row stride (floats); data at col w+4
#define NT   256

__global__ __launch_bounds__(NT)
void depenl_tile(const float* __restrict__ key,
                 const float* __restrict__ query,
                 float* __restrict__ out1,
                 float* __restrict__ out2) {
    __shared__ float sK[NR * RS];
    __shared__ float sQ[NR * RS];

    const int bx    = blockIdx.x;
    const int ch    = bx >> 3;      // 0..255  (B*C)
    const int chunk = bx & 7;       // 0..7
    const int h0    = chunk * HC;
    const int tid   = threadIdx.x;

    const float* __restrict__ kb = key   + (size_t)ch * LL;
    const float* __restrict__ qb = query + (size_t)ch * LL;

    // zero entire smem (covers pad cols, out-of-image halo rows)
    for (int idx = tid; idx < NR * RS; idx += NT) { sK[idx] = 0.f; sQ[idx] = 0.f; }
    __syncthreads();

    // fill valid rows: gh = h0-2+r, cols [4, 132) <- x[gh, 0..127]
    for (int t = tid; t < NR * 32; t += NT) {
        const int r  = t >> 5;
        const int c4 = (t & 31) * 4;
        const int gh = h0 - 2 + r;
        if ((unsigned)gh < 128u) {
            *reinterpret_cast<float4*>(&sK[r * RS + 4 + c4]) =
                *reinterpret_cast<const float4*>(kb + gh * WW + c4);
            *reinterpret_cast<float4*>(&sQ[r * RS + 4 + c4]) =
                *reinterpret_cast<const float4*>(qb + gh * WW + c4);
        }
    }
    __syncthreads();

    const int l0 = h0 * WW;
    float* __restrict__ o1c = out1 + (size_t)ch * MM;
    float* __restrict__ o2c = out2 + (size_t)ch * MM;

    for (int p = 0; p < 9; ++p) {
        const int i = (p * 11) >> 5;     // p/3
        const int j = p - i * 3;         // p%3
        int r = (4 * p + l0 + tid) % 9;  // (4p+l) mod 9, updated incrementally
        int l_loc = tid;                 // l - l0
        float* o1 = o1c + p * LL + l0 + tid;
        float* o2 = o2c + p * LL + l0 + tid;

        #pragma unroll
        for (int it = 0; it < (HC * WW) / NT; ++it) {
            const int h_loc = l_loc >> 7;          // 0..15
            const int w     = l_loc & 127;
            const int nofs  = (h_loc + i + 1) * RS + (w + j + 3);
            const float kn = sK[nofs];
            const float qn = sQ[nofs];

            const int d      = 4 - r;
            const int lc_loc = l_loc + d;          // may be -4..HC*128+3
            const int glc    = l0 + lc_loc;
            float kc, qc;
            if ((unsigned)glc < (unsigned)LL) {
                // same-p center; arithmetic >>/& handle lc_loc<0 correctly
                const int cofs = ((lc_loc >> 7) + i + 1) * RS
                               + ((lc_loc & 127) + j + 3);
                kc = sK[cofs];
                qc = sQ[cofs];
            } else {
                // rare: center falls in adjacent p-plane
                const int m   = p * LL + glc - d;  // p*LL + l
                const int mc  = m + d;
                const int pc  = mc >> 14;
                const int lc2 = mc & 16383;
                const int ic  = (pc * 11) >> 5;
                const int jc  = pc - ic * 3;
                const int hc2 = (lc2 >> 7) + ic - 1;
                const int wc2 = (lc2 & 127) + jc - 1;
                const bool ok = ((unsigned)hc2 < 128u) && ((unsigned)wc2 < 128u);
                const int gi  = (hc2 << 7) + wc2;
                kc = ok ? __ldg(kb + gi) : 0.f;
                qc = ok ? __ldg(qb + gi) : 0.f;
            }

            *o1 = kn * qc;
            *o2 = kc * qn;

            o1 += NT; o2 += NT;
            l_loc += NT;
            r += 4; if (r >= 9) r -= 9;
        }
    }
}

extern "C" void kernel_launch(void* const* d_in, const int* in_sizes, int n_in,
                              void* d_out, int out_size) {
    const float* key   = (const float*)d_in[0];
    const float* query = (const float*)d_in[1];
    float* out1 = (float*)d_out;
    float* out2 = out1 + (size_t)256 * MM;

    depenl_tile<<<256 * 8, NT>>>(key, query, out1, out2);
}